// round 1
// baseline (speedup 1.0000x reference)
#include <cuda_runtime.h>

// EMA recurrence h_t = (1-a)*y_t + a*h_{t-1}, a=0.9, over (B=4, S=4096, D=2048) fp32.
// Parallelized across S via truncated-history chunks: alpha^128 ~ 1.4e-6, so each
// chunk of L=256 outputs is computed exactly enough by warming up over the
// preceding W=128 inputs starting from h=0.

#define EMA_B 4
#define EMA_S 4096
#define EMA_D 2048
#define EMA_DH (EMA_D / 2)          // float2 columns per (b)
#define EMA_COLS (EMA_B * EMA_DH)   // 4096 float2 chains
#define EMA_L 256                   // outputs per chunk
#define EMA_W 128                   // warm-up steps
#define EMA_NC (EMA_S / EMA_L)      // 16 chunks
#define EMA_UNROLL 8

__global__ __launch_bounds__(128, 8)
void ema_chunk_kernel(const float2* __restrict__ y, float2* __restrict__ out) {
    const float A = 0.9f;
    const float Bc = 1.0f - A;   // ~0.1f

    int tid = blockIdx.x * 128 + threadIdx.x;          // [0, EMA_COLS*EMA_NC)
    int chunk = tid / EMA_COLS;                        // whole block shares chunk (4096 % 128 == 0)
    int col   = tid - chunk * EMA_COLS;
    int b     = col / EMA_DH;
    int d     = col - b * EMA_DH;

    const float2* yp = y   + (long)b * EMA_S * EMA_DH + d;
    float2*       op = out + (long)b * EMA_S * EMA_DH + d;

    int start = chunk * EMA_L;

    float hx = 0.0f, hy = 0.0f;

    // Warm-up: run recurrence over [start-W, start) without storing.
    if (chunk > 0) {
        int ws = start - EMA_W;
        for (int s = ws; s < start; s += EMA_UNROLL) {
            float2 v[EMA_UNROLL];
#pragma unroll
            for (int i = 0; i < EMA_UNROLL; i++)
                v[i] = __ldg(&yp[(long)(s + i) * EMA_DH]);
#pragma unroll
            for (int i = 0; i < EMA_UNROLL; i++) {
                hx = fmaf(A, hx, Bc * v[i].x);
                hy = fmaf(A, hy, Bc * v[i].y);
            }
        }
    }

    // Main: compute and store L outputs.
    for (int s = start; s < start + EMA_L; s += EMA_UNROLL) {
        float2 v[EMA_UNROLL];
#pragma unroll
        for (int i = 0; i < EMA_UNROLL; i++)
            v[i] = __ldg(&yp[(long)(s + i) * EMA_DH]);
#pragma unroll
        for (int i = 0; i < EMA_UNROLL; i++) {
            hx = fmaf(A, hx, Bc * v[i].x);
            hy = fmaf(A, hy, Bc * v[i].y);
            op[(long)(s + i) * EMA_DH] = make_float2(hx, hy);
        }
    }
}

extern "C" void kernel_launch(void* const* d_in, const int* in_sizes, int n_in,
                              void* d_out, int out_size) {
    (void)in_sizes; (void)n_in; (void)out_size;
    const float2* y = (const float2*)d_in[0];
    float2* out = (float2*)d_out;

    int total_threads = EMA_COLS * EMA_NC;   // 65536
    int block = 128;
    int grid = total_threads / block;        // 512
    ema_chunk_kernel<<<grid, block>>>(y, out);
}